// round 9
// baseline (speedup 1.0000x reference)
#include <cuda_runtime.h>
#include <cuda_fp16.h>
#include <math.h>
#include <stdint.h>

#define HDIM 128
#define MAXM 1000
#define MAXJ 5000
#define MAXN 200000
#define TILE_OPS 128
#define MAXT 1600

#define RTH2  512

// ------------------------------ scratch ------------------------------------
__device__ __align__(16) float  g_g[HDIM];
__device__ __align__(16) __half g_Ah[MAXM * HDIM];   // fp16 A rows
__device__ __align__(16) __half g_Bh[MAXJ * HDIM];   // fp16 B rows
__device__ float  g_pmax[MAXT];
__device__ int    g_pidx[MAXT];
__device__ double g_pZ[MAXT];
__device__ double g_pS1[MAXT];
// W1^T (rows = output h, cols = k), fp16, blocked-SW128 layout (32KB).
__device__ __align__(16) unsigned char g_W1T[32768];

// --------------------------- helpers ---------------------------------------
__device__ __forceinline__ uint32_t smem_u32(const void* p) {
    uint32_t a;
    asm("{ .reg .u64 t; cvta.to.shared.u64 t, %1; cvt.u32.u64 %0, t; }"
        : "=r"(a) : "l"(p));
    return a;
}

// swizzled byte offset in a 128row x 128col fp16 blocked-SW128 tile
__device__ __forceinline__ uint32_t tile_off(int row, int col) {
    uint32_t off = (uint32_t)(((row >> 3) + ((col >> 6) << 4)) * 1024
                              + (row & 7) * 128 + (col & 63) * 2);
    return off ^ ((off >> 3) & 0x70);
}

__device__ __forceinline__ void ldsm4(uint32_t* r, uint32_t addr) {
    asm volatile("ldmatrix.sync.aligned.m8n8.x4.shared.b16 {%0,%1,%2,%3}, [%4];"
                 : "=r"(r[0]), "=r"(r[1]), "=r"(r[2]), "=r"(r[3]) : "r"(addr));
}
__device__ __forceinline__ void mma_f16(float* d, const uint32_t* a,
                                        uint32_t b0, uint32_t b1) {
    asm volatile("mma.sync.aligned.m16n8k16.row.col.f32.f16.f16.f32 "
                 "{%0,%1,%2,%3}, {%4,%5,%6,%7}, {%8,%9}, {%0,%1,%2,%3};"
                 : "+f"(d[0]), "+f"(d[1]), "+f"(d[2]), "+f"(d[3])
                 : "r"(a[0]), "r"(a[1]), "r"(a[2]), "r"(a[3]), "r"(b0), "r"(b1));
}

// ---------------------------------------------------------------------------
// Kernel 0: g[h] = b0[h] + x_graph @ W0[:2H]
// ---------------------------------------------------------------------------
__global__ void kern_g(const float* __restrict__ x_graph,
                       const float* __restrict__ W0,
                       const float* __restrict__ b0)
{
    __shared__ float xs[2 * HDIM];
    int h = threadIdx.x;
    xs[h] = x_graph[h];
    xs[h + HDIM] = x_graph[h + HDIM];
    __syncthreads();
    float acc = b0[h];
    #pragma unroll 8
    for (int k = 0; k < 2 * HDIM; ++k)
        acc = fmaf(xs[k], W0[k * HDIM + h], acc);
    g_g[h] = acc;
}

// ---------------------------------------------------------------------------
// Kernel 1: A[m][h] = g[h] + x_m[m] @ W0[2H:3H];  B[j][h] = x_job[j] @ W0[3H:4H]
// fp32 accumulate, store fp16.
// ---------------------------------------------------------------------------
__global__ void kern_AB(const float* __restrict__ x_m,
                        const float* __restrict__ x_job,
                        const float* __restrict__ W0,
                        int M, int J)
{
    __shared__ float xs[HDIM];
    int h = threadIdx.x;
    int r = blockIdx.x;
    const float* src; const float* w; __half* dst; float acc;
    if (r < M) {
        src = x_m + (size_t)r * HDIM;
        w   = W0 + (size_t)(2 * HDIM) * HDIM;
        dst = g_Ah + (size_t)r * HDIM;
        acc = g_g[h];
    } else {
        int j = r - M;
        src = x_job + (size_t)j * HDIM;
        w   = W0 + (size_t)(3 * HDIM) * HDIM;
        dst = g_Bh + (size_t)j * HDIM;
        acc = 0.0f;
    }
    xs[h] = src[h];
    __syncthreads();
    #pragma unroll 8
    for (int k = 0; k < HDIM; ++k)
        acc = fmaf(xs[k], w[k * HDIM + h], acc);
    dst[h] = __float2half(acc);
}

// ---------------------------------------------------------------------------
// Kernel 1b: W1^T -> fp16 in blocked-SW128 layout.  Row r = output h, col c = k.
// ---------------------------------------------------------------------------
__global__ void kern_w1prep(const float* __restrict__ W1)
{
    int idx = blockIdx.x * blockDim.x + threadIdx.x;   // 0..16383
    int r = idx >> 7;
    int c = idx & 127;
    float w = W1[c * HDIM + r];
    *(__half*)(g_W1T + tile_off(r, c)) = __float2half(w);
}

// ---------------------------------------------------------------------------
// Kernel 2: fp16 HMMA tile kernel + fused per-block softmax partials.
// 128 ops/block, 256 threads = 8 warps tiled 2(M) x 4(N):
//   warp (mw, nw) computes rows [mw*64, +64) x cols [nw*32, +32).
// D = h0 @ W1^T (fp32 accum); score = b2 + sum_h relu(b1+D)*W2
// Block emits (max, argmax, Z_b, S1_b) directly.
// ---------------------------------------------------------------------------
#define OFF_A     0
#define OFF_W     32768
#define OFF_SB1   65536
#define OFF_SW2   66048
#define OFF_PART  66560      // 4 x 128 floats
#define OFF_WRED  68608      // warp-reduction scratch
#define SMEM_TILE_TOTAL 68736

__global__ void __launch_bounds__(256, 2)
kern_tile(const int* __restrict__ m_ids,
          const int* __restrict__ job_idx,
          const float* __restrict__ b1,
          const float* __restrict__ W2,
          const float* __restrict__ b2,
          int n)
{
    extern __shared__ char smem[];
    uint32_t sb = smem_u32(smem);
    int tid = threadIdx.x;
    int wid = tid >> 5;
    int lid = tid & 31;
    int base = blockIdx.x * TILE_OPS;

    // ---- copy pre-swizzled W tile (32KB) ----
    {
        const uint4* src = (const uint4*)g_W1T;
        uint4* dst = (uint4*)(smem + OFF_W);
        #pragma unroll
        for (int i = 0; i < 8; ++i)
            dst[tid + 256 * i] = src[tid + 256 * i];
    }
    if (tid < HDIM) {
        ((float*)(smem + OFF_SB1))[tid] = b1[tid];
        ((float*)(smem + OFF_SW2))[tid] = W2[tid];
    }

    // ---- stage 1: gather h0 = relu(A[m]+B[j]) -> fp16 smem tile ----
    {
        int c0 = lid * 4;                 // this lane's 4 k-columns
        uint32_t colpart = (uint32_t)(((c0 >> 6) << 4) * 1024 + (c0 & 63) * 2);
        #pragma unroll 4
        for (int i = 0; i < 16; ++i) {
            int t = wid * 16 + i;
            int op = base + t;
            int m = 0, j = 0;
            if (op < n) { m = m_ids[op]; j = job_idx[op]; }
            uint2 ua = *(const uint2*)(g_Ah + m * HDIM + c0);
            uint2 ub = *(const uint2*)(g_Bh + j * HDIM + c0);
            float2 a0 = __half22float2(*(const half2*)&ua.x);
            float2 a1 = __half22float2(*(const half2*)&ua.y);
            float2 b0f = __half22float2(*(const half2*)&ub.x);
            float2 b1f = __half22float2(*(const half2*)&ub.y);
            float v0 = fmaxf(a0.x + b0f.x, 0.0f);
            float v1 = fmaxf(a0.y + b0f.y, 0.0f);
            float v2 = fmaxf(a1.x + b1f.x, 0.0f);
            float v3 = fmaxf(a1.y + b1f.y, 0.0f);
            half2 r0 = __floats2half2_rn(v0, v1);
            half2 r1 = __floats2half2_rn(v2, v3);
            uint32_t off = colpart + (uint32_t)(((t >> 3) << 10) + (t & 7) * 128);
            uint32_t sw = off ^ ((off >> 3) & 0x70);
            uint2 pv;
            pv.x = *(const uint32_t*)&r0;
            pv.y = *(const uint32_t*)&r1;
            *(uint2*)(smem + OFF_A + sw) = pv;
        }
    }
    __syncthreads();

    // ---- precomputed swizzled addresses ----
    int mw = wid >> 2;               // 0..1  (M group)
    int nw = wid & 3;                // 0..3  (N group)
    int lane7 = lid & 7;
    uint32_t xm = (uint32_t)(lane7 << 4);          // constant swizzle XOR per lane
    uint32_t acol2 = (uint32_t)((lid >> 4) * 16);  // A k-byte offset
    uint32_t bcol2 = (uint32_t)(((lid >> 3) & 1) * 16);
    uint32_t dx = acol2 ^ bcol2;
    int arow15 = lid & 15;
    int brow_in = ((lid >> 4) << 3) + lane7;

    uint32_t Abig[4], Bbig[2], lowA[8];
    #pragma unroll
    for (int mi = 0; mi < 4; ++mi) {
        int r = mw * 64 + mi * 16 + arow15;
        Abig[mi] = sb + OFF_A + (uint32_t)((r >> 3) * 1024 + (r & 7) * 128);
    }
    #pragma unroll
    for (int ni = 0; ni < 2; ++ni) {
        int r = nw * 32 + ni * 16 + brow_in;
        Bbig[ni] = sb + OFF_W + (uint32_t)((r >> 3) * 1024 + (r & 7) * 128);
    }
    #pragma unroll
    for (int kc = 0; kc < 8; ++kc) {
        uint32_t at = (kc >= 4) ? 16384u : 0u;
        lowA[kc] = (((uint32_t)((kc & 3) * 32) + acol2) ^ xm) + at;
    }

    // ---- mainloop: 8 k-chunks; per kc: 4 A-frags, 2 B-frags, 16 MMAs ----
    float d[4][4][4];
    #pragma unroll
    for (int mi = 0; mi < 4; ++mi)
        #pragma unroll
        for (int ni = 0; ni < 4; ++ni)
            #pragma unroll
            for (int q = 0; q < 4; ++q) d[mi][ni][q] = 0.0f;

    #pragma unroll
    for (int kc = 0; kc < 8; ++kc) {
        uint32_t a[4][4], b[2][4];
        uint32_t lowB = lowA[kc] ^ dx;
        #pragma unroll
        for (int mi = 0; mi < 4; ++mi) ldsm4(a[mi], Abig[mi] + lowA[kc]);
        #pragma unroll
        for (int ni = 0; ni < 2; ++ni) ldsm4(b[ni], Bbig[ni] + lowB);
        #pragma unroll
        for (int mi = 0; mi < 4; ++mi) {
            mma_f16(d[mi][0], a[mi], b[0][0], b[0][1]);
            mma_f16(d[mi][1], a[mi], b[0][2], b[0][3]);
            mma_f16(d[mi][2], a[mi], b[1][0], b[1][1]);
            mma_f16(d[mi][3], a[mi], b[1][2], b[1][3]);
        }
    }

    // ---- epilogue A: relu(+b1)*W2, per-warp 32-col partials ----
    {
        const float* sb1 = (const float*)(smem + OFF_SB1);
        const float* sw2 = (const float*)(smem + OFF_SW2);
        float* part = (float*)(smem + OFF_PART);
        int g = lid >> 2;
        int t4 = lid & 3;
        unsigned mask = 0xffffffffu;
        #pragma unroll
        for (int mi = 0; mi < 4; ++mi) {
            float s0 = 0.0f, s1 = 0.0f;
            #pragma unroll
            for (int ni = 0; ni < 4; ++ni) {
                int c0 = nw * 32 + ni * 8 + 2 * t4;
                float bb0 = sb1[c0], bb1 = sb1[c0 + 1];
                float w0 = sw2[c0], w1 = sw2[c0 + 1];
                s0 = fmaf(fmaxf(d[mi][ni][0] + bb0, 0.0f), w0, s0);
                s0 = fmaf(fmaxf(d[mi][ni][1] + bb1, 0.0f), w1, s0);
                s1 = fmaf(fmaxf(d[mi][ni][2] + bb0, 0.0f), w0, s1);
                s1 = fmaf(fmaxf(d[mi][ni][3] + bb1, 0.0f), w1, s1);
            }
            s0 += __shfl_xor_sync(mask, s0, 1);
            s0 += __shfl_xor_sync(mask, s0, 2);
            s1 += __shfl_xor_sync(mask, s1, 1);
            s1 += __shfl_xor_sync(mask, s1, 2);
            if (t4 == 0) {
                int row = mw * 64 + mi * 16 + g;
                part[nw * 128 + row] = s0;
                part[nw * 128 + row + 8] = s1;
            }
        }
    }
    __syncthreads();

    // ---- epilogue B: per-block softmax partial (max/argmax, Z, S1) ----
    {
        float* wred_f = (float*)(smem + OFF_WRED);          // wmax[4]
        int*   wred_i = (int*)(smem + OFF_WRED + 16);       // widx[4]
        double* wred_z = (double*)(smem + OFF_WRED + 32);   // wZ[4]
        double* wred_s = (double*)(smem + OFF_WRED + 64);   // wS1[4]
        unsigned mask = 0xffffffffu;

        float myscore = -INFINITY;
        int myidx = 0x7fffffff;
        if (tid < TILE_OPS) {
            const float* part = (const float*)(smem + OFF_PART);
            int op = base + tid;
            if (op < n) {
                myscore = part[tid] + part[128 + tid] + part[256 + tid] +
                          part[384 + tid] + b2[0];
                myidx = op;
            }
        }
        if (tid < TILE_OPS) {
            float v = myscore; int bi = myidx;
            #pragma unroll
            for (int off = 16; off > 0; off >>= 1) {
                float vo = __shfl_xor_sync(mask, v, off);
                int io = __shfl_xor_sync(mask, bi, off);
                if (vo > v || (vo == v && io < bi)) { v = vo; bi = io; }
            }
            if (lid == 0) { wred_f[wid] = v; wred_i[wid] = bi; }
        }
        __syncthreads();
        if (tid == 0) {
            float v = wred_f[0]; int bi = wred_i[0];
            #pragma unroll
            for (int w = 1; w < 4; ++w) {
                float vo = wred_f[w]; int io = wred_i[w];
                if (vo > v || (vo == v && io < bi)) { v = vo; bi = io; }
            }
            wred_f[0] = v; wred_i[0] = bi;
        }
        __syncthreads();
        float bmx = wred_f[0];
        if (tid < TILE_OPS) {
            float tt = myscore - bmx;
            float e = expf(tt);
            double z = (double)e;
            double s1d = (e > 0.0f) ? (double)tt * (double)e : 0.0;
            #pragma unroll
            for (int off = 16; off > 0; off >>= 1) {
                z   += __shfl_xor_sync(mask, z, off);
                s1d += __shfl_xor_sync(mask, s1d, off);
            }
            if (lid == 0) { wred_z[wid] = z; wred_s[wid] = s1d; }
        }
        __syncthreads();
        if (tid == 0) {
            double Z = wred_z[0] + wred_z[1] + wred_z[2] + wred_z[3];
            double S1 = wred_s[0] + wred_s[1] + wred_s[2] + wred_s[3];
            g_pmax[blockIdx.x] = bmx;
            g_pidx[blockIdx.x] = wred_i[0];
            g_pZ[blockIdx.x]   = Z;
            g_pS1[blockIdx.x]  = S1;
        }
    }
}

// ---------------------------------------------------------------------------
// Kernel 3: combine nblk partials (softmax-merge, fixed order -> deterministic)
// ---------------------------------------------------------------------------
__global__ void __launch_bounds__(RTH2)
kern_reduce(int nblk, float* __restrict__ out)
{
    __shared__ float  sv[RTH2];
    __shared__ int    si[RTH2];
    __shared__ double sz[RTH2];
    __shared__ double ss[RTH2];

    int tid = threadIdx.x;

    float best = -INFINITY;
    int bi = 0x7fffffff;
    for (int i = tid; i < nblk; i += RTH2) {
        float v = g_pmax[i];
        int io = g_pidx[i];
        if (v > best || (v == best && io < bi)) { best = v; bi = io; }
    }
    sv[tid] = best; si[tid] = bi;
    __syncthreads();
    for (int s = RTH2 / 2; s > 0; s >>= 1) {
        if (tid < s) {
            float vo = sv[tid + s]; int io = si[tid + s];
            if (vo > sv[tid] || (vo == sv[tid] && io < si[tid])) {
                sv[tid] = vo; si[tid] = io;
            }
        }
        __syncthreads();
    }
    float mx = sv[0];
    int idx = si[0];
    __syncthreads();

    double z = 0.0, s1 = 0.0;
    for (int i = tid; i < nblk; i += RTH2) {
        double zb = g_pZ[i];
        double dd = (double)g_pmax[i] - (double)mx;
        double w = exp(dd);
        z  += w * zb;
        s1 += w * (g_pS1[i] + dd * zb);
    }
    sz[tid] = z; ss[tid] = s1;
    __syncthreads();
    for (int s = RTH2 / 2; s > 0; s >>= 1) {
        if (tid < s) { sz[tid] += sz[tid + s]; ss[tid] += ss[tid + s]; }
        __syncthreads();
    }
    if (tid == 0) {
        double Z = sz[0], S1 = ss[0];
        double logZ = log(Z);
        out[0] = (float)idx;
        out[1] = (float)(1.0 / Z);
        out[2] = (float)(-logZ);
        out[3] = (float)(logZ - S1 / Z);
    }
}

// ---------------------------------------------------------------------------
extern "C" void kernel_launch(void* const* d_in, const int* in_sizes, int n_in,
                              void* d_out, int out_size)
{
    const float* x_graph = (const float*)d_in[0];
    const float* x_m     = (const float*)d_in[1];
    const float* x_job   = (const float*)d_in[2];
    const int*   m_ids   = (const int*)  d_in[3];
    const int*   job_idx = (const int*)  d_in[4];
    const float* W0      = (const float*)d_in[5];
    const float* b0      = (const float*)d_in[6];
    const float* W1      = (const float*)d_in[7];
    const float* b1      = (const float*)d_in[8];
    const float* W2      = (const float*)d_in[9];
    const float* b2      = (const float*)d_in[10];

    int n = in_sizes[3];
    int M = in_sizes[1] / HDIM;
    int J = in_sizes[2] / HDIM;
    int tiles = (n + TILE_OPS - 1) / TILE_OPS;

    cudaFuncSetAttribute(kern_tile, cudaFuncAttributeMaxDynamicSharedMemorySize,
                         SMEM_TILE_TOTAL);

    kern_g<<<1, HDIM>>>(x_graph, W0, b0);
    kern_AB<<<M + J, HDIM>>>(x_m, x_job, W0, M, J);
    kern_w1prep<<<64, 256>>>(W1);
    kern_tile<<<tiles, 256, SMEM_TILE_TOTAL>>>(m_ids, job_idx, b1, W2, b2, n);
    kern_reduce<<<1, RTH2>>>(tiles, (float*)d_out);
}